// round 5
// baseline (speedup 1.0000x reference)
#include <cuda_runtime.h>

// GCN_18760417149681 — fully linear GraphSAGE collapse, single persistent kernel.
// out[m] = inv[m]*SB[m] + xs[m] + (deg[m]>0)*CB + C2
// SB = sum over in-edges of (SA[src]/max(deg[src],1) + xg[src]),
// SA = sum over in-edges of xp[src]; xp/xg/xs = x[node] . {p,g,s},
// p,g,s 64-vectors precomputed from the (entirely linear) network weights.

#define NMAX   100000
#define NFEAT  64
#define NHID   128
#define NBLK   296          // 2 blocks * 148 SMs (GB300 has 152) — all resident
#define TPB    1024

// ---- precomputed small vectors / consts ----
__device__ __align__(16) float g_P[NFEAT];
__device__ __align__(16) float g_G[NFEAT];
__device__ __align__(16) float g_S[NFEAT];
__device__ float g_C[2];     // [0]=cb (gated by deg>0), [1]=c2 (always)
__device__ int   g_is64;

// ---- per-node scratch ----
__device__ float  g_XP[NMAX];
__device__ float  g_XG[NMAX];
__device__ float  g_XS[NMAX];
__device__ __align__(8) float2 g_ACC[NMAX];   // (SA, deg) atomic target
__device__ float  g_Z[NMAX];
__device__ float  g_SB[NMAX];

// ---- grid barrier state (self-resetting across graph replays) ----
__device__ unsigned g_bar_count = 0;
__device__ volatile unsigned g_bar_gen = 0;

__device__ __forceinline__ void grid_barrier()
{
    __syncthreads();
    if (threadIdx.x == 0) {
        unsigned gen = g_bar_gen;
        __threadfence();                                   // release prior writes
        if (atomicInc(&g_bar_count, NBLK - 1) == NBLK - 1) {
            __threadfence();
            g_bar_gen = gen + 1;                           // release all waiters
        } else {
            while (g_bar_gen == gen) { __nanosleep(64); }
        }
        __threadfence();                                   // acquire
    }
    __syncthreads();
}

__global__ void __launch_bounds__(TPB, 2) k_fused(
    const float* __restrict__ x, const int* __restrict__ ei32,
    const float* __restrict__ Wl1, const float* __restrict__ Wr1,
    const float* __restrict__ b1,
    const float* __restrict__ Wl2, const float* __restrict__ Wr2,
    const float* __restrict__ b2,
    const float* __restrict__ Wfc1, const float* __restrict__ bfc1,
    const float* __restrict__ Wfc2, const float* __restrict__ bfc2,
    float* __restrict__ out, int N, int E)
{
    const unsigned tid = blockIdx.x * TPB + threadIdx.x;
    const unsigned T   = NBLK * TPB;

    // ================= phase 0: prep (block 0) + zero (other blocks) =================
    if (blockIdx.x == 0) {
        __shared__ float sw[NHID], su[NHID], sv[NHID];
        int t = threadIdx.x;

        if (t == 0) {   // dtype sniff: int64 LE small indices => odd words all zero
            int odd_nonzero = 0;
            for (int k = 0; k < 64; k++) {
                long long pos = (1 + (long long)k * ((2LL * E - 2) / 64)) | 1;
                if (ei32[pos] != 0) odd_nonzero++;
            }
            g_is64 = (odd_nonzero == 0) ? 1 : 0;
        }

        if (t < NHID) {
            float acc = 0.f;
            #pragma unroll
            for (int c = 0; c < 32; c++) acc += Wfc1[t * 32 + c] * Wfc2[c];
            sw[t] = acc;
        }
        __syncthreads();
        if (t < NHID) {
            float au = 0.f, av = 0.f;
            #pragma unroll 4
            for (int j = 0; j < NHID; j++) {
                float wv = sw[j];
                au += Wl2[t * NHID + j] * wv;
                av += Wr2[t * NHID + j] * wv;
            }
            su[t] = au; sv[t] = av;
        }
        __syncthreads();
        if (t < NFEAT) {
            float p = 0.f, g = 0.f, s = 0.f;
            #pragma unroll 4
            for (int j = 0; j < NHID; j++) {
                float wl = Wl1[t * NHID + j];
                float wr = Wr1[t * NHID + j];
                float uj = su[j], vj = sv[j];
                p += wl * uj;
                g += wr * uj + wl * vj;
                s += wr * vj;
            }
            g_P[t] = p; g_G[t] = g; g_S[t] = s;
        }
        if (t == 0) {
            float cb = 0.f, c2 = 0.f;
            for (int j = 0; j < NHID; j++) {
                cb += b1[j] * su[j];
                c2 += b1[j] * sv[j] + b2[j] * sw[j];
            }
            for (int c = 0; c < 32; c++) c2 += bfc1[c] * Wfc2[c];
            c2 += bfc2[0];
            g_C[0] = cb; g_C[1] = c2;
        }
    } else {
        for (int i = (blockIdx.x - 1) * TPB + threadIdx.x; i < N;
             i += (NBLK - 1) * TPB) {
            g_ACC[i] = make_float2(0.f, 0.f);
            g_SB[i]  = 0.f;
        }
    }
    grid_barrier();

    // ================= phase 1: passA — warp per node, 3 dots =================
    {
        unsigned warp = tid >> 5, lane = tid & 31, nw = T >> 5;
        float2 pv = ((const float2*)g_P)[lane];
        float2 gv = ((const float2*)g_G)[lane];
        float2 sv = ((const float2*)g_S)[lane];
        for (unsigned node = warp; node < (unsigned)N; node += nw) {
            float2 xv = __ldg(((const float2*)x) + (size_t)node * 32 + lane);
            float xp = xv.x * pv.x + xv.y * pv.y;
            float xg = xv.x * gv.x + xv.y * gv.y;
            float xs = xv.x * sv.x + xv.y * sv.y;
            #pragma unroll
            for (int off = 16; off; off >>= 1) {
                xp += __shfl_xor_sync(0xffffffffu, xp, off);
                xg += __shfl_xor_sync(0xffffffffu, xg, off);
                xs += __shfl_xor_sync(0xffffffffu, xs, off);
            }
            if (lane == 0) {
                g_XP[node] = xp;
                g_XG[node] = xg;
                g_XS[node] = xs;
            }
        }
    }
    grid_barrier();

    // ================= phase 2: scatter1 — (SA, deg) float2 atomics =================
    {
        int is64 = g_is64;
        for (long long base = (long long)tid * 2; base < E; base += (long long)T * 2) {
            bool two = (base + 1 < E);
            int s0, d0, s1 = 0, d1 = 0;
            if (is64) {
                longlong2 ss = __ldg((const longlong2*)((const long long*)ei32 + base));
                longlong2 dd = __ldg((const longlong2*)((const long long*)ei32 + E + base));
                s0 = (int)ss.x; s1 = (int)ss.y; d0 = (int)dd.x; d1 = (int)dd.y;
            } else {
                int2 ss = __ldg((const int2*)(ei32 + base));
                int2 dd = __ldg((const int2*)(ei32 + E + base));
                s0 = ss.x; s1 = ss.y; d0 = dd.x; d1 = dd.y;
            }
            float xp0 = __ldg(&g_XP[s0]);
            float xp1 = two ? __ldg(&g_XP[s1]) : 0.f;
            atomicAdd(&g_ACC[d0], make_float2(xp0, 1.0f));
            if (two) atomicAdd(&g_ACC[d1], make_float2(xp1, 1.0f));
        }
    }
    grid_barrier();

    // ================= phase 3: passT — Z = SA/max(deg,1) + xg =================
    for (unsigned i = tid; i < (unsigned)N; i += T) {
        float2 a = g_ACC[i];
        g_Z[i] = a.x * __frcp_rn(fmaxf(a.y, 1.0f)) + g_XG[i];
    }
    grid_barrier();

    // ================= phase 4: scatter2 — SB += Z[src] =================
    {
        int is64 = g_is64;
        for (long long base = (long long)tid * 2; base < E; base += (long long)T * 2) {
            bool two = (base + 1 < E);
            int s0, d0, s1 = 0, d1 = 0;
            if (is64) {
                longlong2 ss = __ldg((const longlong2*)((const long long*)ei32 + base));
                longlong2 dd = __ldg((const longlong2*)((const long long*)ei32 + E + base));
                s0 = (int)ss.x; s1 = (int)ss.y; d0 = (int)dd.x; d1 = (int)dd.y;
            } else {
                int2 ss = __ldg((const int2*)(ei32 + base));
                int2 dd = __ldg((const int2*)(ei32 + E + base));
                s0 = ss.x; s1 = ss.y; d0 = dd.x; d1 = dd.y;
            }
            float z0 = __ldg(&g_Z[s0]);
            float z1 = two ? __ldg(&g_Z[s1]) : 0.f;
            atomicAdd(&g_SB[d0], z0);
            if (two) atomicAdd(&g_SB[d1], z1);
        }
    }
    grid_barrier();

    // ================= phase 5: final =================
    {
        float cb = g_C[0], c2 = g_C[1];
        for (unsigned i = tid; i < (unsigned)N; i += T) {
            float2 a = g_ACC[i];
            float inv = __frcp_rn(fmaxf(a.y, 1.0f));
            float res = inv * g_SB[i] + g_XS[i] + c2;
            if (a.y > 0.0f) res += cb;
            out[i] = res;
        }
    }
}

// ===================== launch =====================
extern "C" void kernel_launch(void* const* d_in, const int* in_sizes, int n_in,
                              void* d_out, int out_size)
{
    const float* x    = (const float*)d_in[0];
    const int*   ei32 = (const int*)d_in[1];   // int32 or int64 — sniffed on device
    // d_in[2] = edge_weight (unused by the reference)
    const float* Wl1  = (const float*)d_in[3];
    const float* Wr1  = (const float*)d_in[4];
    const float* b1   = (const float*)d_in[5];
    const float* Wl2  = (const float*)d_in[6];
    const float* Wr2  = (const float*)d_in[7];
    const float* b2   = (const float*)d_in[8];
    const float* Wfc1 = (const float*)d_in[9];
    const float* bfc1 = (const float*)d_in[10];
    const float* Wfc2 = (const float*)d_in[11];
    const float* bfc2 = (const float*)d_in[12];
    float* out = (float*)d_out;

    int N = in_sizes[0] / NFEAT;   // 100000
    int E = in_sizes[2];           // 1600000 (edge_weight element count)

    k_fused<<<NBLK, TPB>>>(x, ei32, Wl1, Wr1, b1, Wl2, Wr2, b2,
                           Wfc1, bfc1, Wfc2, bfc2, out, N, E);
}

// round 6
// speedup vs baseline: 1.2293x; 1.2293x over previous
#include <cuda_runtime.h>

// GCN_18760417149681 — fully linear GraphSAGE collapse, v5 (5 launches).
// out[m] = inv[m]*SB[m] + xs[m] + (deg[m]>0)*CB + C2
// SB = Σ_in-edges (SA[src]/max(deg[src],1) + xg[src]);  SA = Σ_in-edges xp[src]
// xp/xg/xs = x[node].{p,g,s} with p,g,s precomputed from the (linear) weights.
// Node state packed: ACC4 = (SA, deg, xg, xs); XP separate 4B gather array.

#define NMAX 100000
#define NFEAT 64
#define NHID 128

__device__ __align__(16) float g_P[NFEAT];
__device__ __align__(16) float g_G[NFEAT];
__device__ __align__(16) float g_S[NFEAT];
__device__ float g_C[2];   // [0]=cb (gated by deg>0), [1]=c2
__device__ int   g_is64;

__device__ __align__(16) float4 g_ACC[NMAX];  // (SA, deg, xg, xs) — 1.6MB
__device__ float g_XP[NMAX];                  // 400KB gather set for scatter1
__device__ float g_SB[NMAX];                  // 400KB atomic target

// ===================== prep: collapse weights + dtype sniff =====================
__global__ void k_prep(const float* __restrict__ Wl1, const float* __restrict__ Wr1,
                       const float* __restrict__ b1,
                       const float* __restrict__ Wl2, const float* __restrict__ Wr2,
                       const float* __restrict__ b2,
                       const float* __restrict__ Wfc1, const float* __restrict__ bfc1,
                       const float* __restrict__ Wfc2, const float* __restrict__ bfc2,
                       const int* __restrict__ ei32, int E)
{
    __shared__ float sw[NHID], su[NHID], sv[NHID];
    int t = threadIdx.x;  // 0..127

    if (t == 0) {   // int64 LE small indices => odd 32-bit words all zero
        int odd_nonzero = 0;
        for (int k = 0; k < 64; k++) {
            long long pos = (1 + (long long)k * ((2LL * E - 2) / 64)) | 1;
            if (ei32[pos] != 0) odd_nonzero++;
        }
        g_is64 = (odd_nonzero == 0) ? 1 : 0;
    }

    float acc = 0.f;
    #pragma unroll
    for (int c = 0; c < 32; c++) acc += Wfc1[t * 32 + c] * Wfc2[c];
    sw[t] = acc;
    __syncthreads();

    float au = 0.f, av = 0.f;
    #pragma unroll 4
    for (int j = 0; j < NHID; j++) {
        float wv = sw[j];
        au += Wl2[t * NHID + j] * wv;
        av += Wr2[t * NHID + j] * wv;
    }
    su[t] = au; sv[t] = av;
    __syncthreads();

    if (t < NFEAT) {
        float p = 0.f, g = 0.f, s = 0.f;
        #pragma unroll 4
        for (int j = 0; j < NHID; j++) {
            float wl = Wl1[t * NHID + j];
            float wr = Wr1[t * NHID + j];
            float uj = su[j], vj = sv[j];
            p += wl * uj;
            g += wr * uj + wl * vj;
            s += wr * vj;
        }
        g_P[t] = p; g_G[t] = g; g_S[t] = s;
    }

    if (t == 0) {
        float cb = 0.f, c2 = 0.f;
        for (int j = 0; j < NHID; j++) {
            cb += b1[j] * su[j];
            c2 += b1[j] * sv[j] + b2[j] * sw[j];
        }
        for (int c = 0; c < 32; c++) c2 += bfc1[c] * Wfc2[c];
        c2 += bfc2[0];
        g_C[0] = cb; g_C[1] = c2;
    }
}

// ===================== pass A: dots + init node state =====================
// half-warp (16 lanes) per node; lane covers one float4 (4 feats).
__global__ void __launch_bounds__(256) k_passA(const float* __restrict__ x, int n)
{
    int node = (blockIdx.x * blockDim.x + threadIdx.x) >> 4;
    int lane = threadIdx.x & 15;
    if (node >= n) return;

    float4 xv = __ldg(((const float4*)x) + (long long)node * 16 + lane);
    float4 pv = ((const float4*)g_P)[lane];
    float4 gv = ((const float4*)g_G)[lane];
    float4 sv = ((const float4*)g_S)[lane];

    float xp = xv.x * pv.x + xv.y * pv.y + xv.z * pv.z + xv.w * pv.w;
    float xg = xv.x * gv.x + xv.y * gv.y + xv.z * gv.z + xv.w * gv.w;
    float xs = xv.x * sv.x + xv.y * sv.y + xv.z * sv.z + xv.w * sv.w;

    #pragma unroll
    for (int off = 8; off; off >>= 1) {
        xp += __shfl_xor_sync(0xffffffffu, xp, off);
        xg += __shfl_xor_sync(0xffffffffu, xg, off);
        xs += __shfl_xor_sync(0xffffffffu, xs, off);
    }
    if (lane == 0) {
        g_XP[node]  = xp;
        g_ACC[node] = make_float4(0.f, 0.f, xg, xs);
        g_SB[node]  = 0.f;
    }
}

// ===================== index fetch helper: 4 edges =====================
__device__ __forceinline__ void load4(const int* __restrict__ ei32, long long E,
                                      long long base, int is64,
                                      int (&s)[4], int (&d)[4])
{
    if (is64) {
        const long long* p = (const long long*)ei32;
        longlong2 a = __ldg((const longlong2*)(p + base));
        longlong2 b = __ldg((const longlong2*)(p + base + 2));
        longlong2 c = __ldg((const longlong2*)(p + E + base));
        longlong2 e = __ldg((const longlong2*)(p + E + base + 2));
        s[0] = (int)a.x; s[1] = (int)a.y; s[2] = (int)b.x; s[3] = (int)b.y;
        d[0] = (int)c.x; d[1] = (int)c.y; d[2] = (int)e.x; d[3] = (int)e.y;
    } else {
        int4 a = __ldg((const int4*)(ei32 + base));
        int4 c = __ldg((const int4*)(ei32 + E + base));
        s[0] = a.x; s[1] = a.y; s[2] = a.z; s[3] = a.w;
        d[0] = c.x; d[1] = c.y; d[2] = c.z; d[3] = c.w;
    }
}

// ===================== scatter 1: ACC.xy += (xp[src], 1) =====================
__global__ void __launch_bounds__(256) k_scatter1(const int* __restrict__ ei32, int E)
{
    long long base = (long long)(blockIdx.x * blockDim.x + threadIdx.x) * 4;
    if (base >= E) return;
    int is64 = g_is64;

    if (base + 3 < E) {
        int s[4], d[4];
        load4(ei32, E, base, is64, s, d);
        float xp0 = __ldg(&g_XP[s[0]]);
        float xp1 = __ldg(&g_XP[s[1]]);
        float xp2 = __ldg(&g_XP[s[2]]);
        float xp3 = __ldg(&g_XP[s[3]]);
        atomicAdd((float2*)&g_ACC[d[0]], make_float2(xp0, 1.0f));
        atomicAdd((float2*)&g_ACC[d[1]], make_float2(xp1, 1.0f));
        atomicAdd((float2*)&g_ACC[d[2]], make_float2(xp2, 1.0f));
        atomicAdd((float2*)&g_ACC[d[3]], make_float2(xp3, 1.0f));
    } else {
        for (long long e = base; e < E; e++) {
            int src, dst;
            if (is64) {
                src = (int)((const long long*)ei32)[e];
                dst = (int)((const long long*)ei32)[E + e];
            } else {
                src = ei32[e]; dst = ei32[E + e];
            }
            atomicAdd((float2*)&g_ACC[dst], make_float2(__ldg(&g_XP[src]), 1.0f));
        }
    }
}

// ===================== scatter 2: SB[dst] += t[src] + xg[src] =====================
__global__ void __launch_bounds__(256) k_scatter2(const int* __restrict__ ei32, int E)
{
    long long base = (long long)(blockIdx.x * blockDim.x + threadIdx.x) * 4;
    if (base >= E) return;
    int is64 = g_is64;

    if (base + 3 < E) {
        int s[4], d[4];
        load4(ei32, E, base, is64, s, d);
        float4 a0 = __ldg(&g_ACC[s[0]]);
        float4 a1 = __ldg(&g_ACC[s[1]]);
        float4 a2 = __ldg(&g_ACC[s[2]]);
        float4 a3 = __ldg(&g_ACC[s[3]]);
        float z0 = a0.x * __frcp_rn(fmaxf(a0.y, 1.0f)) + a0.z;
        float z1 = a1.x * __frcp_rn(fmaxf(a1.y, 1.0f)) + a1.z;
        float z2 = a2.x * __frcp_rn(fmaxf(a2.y, 1.0f)) + a2.z;
        float z3 = a3.x * __frcp_rn(fmaxf(a3.y, 1.0f)) + a3.z;
        atomicAdd(&g_SB[d[0]], z0);
        atomicAdd(&g_SB[d[1]], z1);
        atomicAdd(&g_SB[d[2]], z2);
        atomicAdd(&g_SB[d[3]], z3);
    } else {
        for (long long e = base; e < E; e++) {
            int src, dst;
            if (is64) {
                src = (int)((const long long*)ei32)[e];
                dst = (int)((const long long*)ei32)[E + e];
            } else {
                src = ei32[e]; dst = ei32[E + e];
            }
            float4 a = __ldg(&g_ACC[src]);
            atomicAdd(&g_SB[dst], a.x * __frcp_rn(fmaxf(a.y, 1.0f)) + a.z);
        }
    }
}

// ===================== final =====================
__global__ void __launch_bounds__(256) k_final(float* __restrict__ out, int n)
{
    int i = blockIdx.x * blockDim.x + threadIdx.x;
    if (i < n) {
        float cb = g_C[0], c2 = g_C[1];
        float4 a = g_ACC[i];
        float inv = __frcp_rn(fmaxf(a.y, 1.0f));
        float res = inv * g_SB[i] + a.w + c2;
        if (a.y > 0.0f) res += cb;
        out[i] = res;
    }
}

// ===================== launch =====================
extern "C" void kernel_launch(void* const* d_in, const int* in_sizes, int n_in,
                              void* d_out, int out_size)
{
    const float* x    = (const float*)d_in[0];
    const int*   ei32 = (const int*)d_in[1];   // int32 or int64 — sniffed on device
    // d_in[2] = edge_weight (unused by the reference)
    const float* Wl1  = (const float*)d_in[3];
    const float* Wr1  = (const float*)d_in[4];
    const float* b1   = (const float*)d_in[5];
    const float* Wl2  = (const float*)d_in[6];
    const float* Wr2  = (const float*)d_in[7];
    const float* b2   = (const float*)d_in[8];
    const float* Wfc1 = (const float*)d_in[9];
    const float* bfc1 = (const float*)d_in[10];
    const float* Wfc2 = (const float*)d_in[11];
    const float* bfc2 = (const float*)d_in[12];
    float* out = (float*)d_out;

    int N = in_sizes[0] / NFEAT;   // 100000
    int E = in_sizes[2];           // 1600000

    k_prep<<<1, 128>>>(Wl1, Wr1, b1, Wl2, Wr2, b2, Wfc1, bfc1, Wfc2, bfc2, ei32, E);

    k_passA<<<(N + 15) / 16, 256>>>(x, N);

    int tb = 256;
    int eb = (E + tb * 4 - 1) / (tb * 4);   // 4 edges per thread
    k_scatter1<<<eb, tb>>>(ei32, E);
    k_scatter2<<<eb, tb>>>(ei32, E);
    k_final<<<(N + tb - 1) / tb, tb>>>(out, N);
}

// round 7
// speedup vs baseline: 1.2958x; 1.0541x over previous
#include <cuda_runtime.h>

// GCN_18760417149681 — fully linear GraphSAGE collapse, v7 (4 launches).
// out[m] = inv[m]*(SB[m] + SG[m]) + xs[m] + (deg[m]>0)*CB + C2
//   ACC[m] = (SA, deg, SG, xs);  scatter1: ACC[dst] += (xp[src], 1, xg[src], 0)
//   scatter2: SB[dst] += SA[src]/max(deg[src],1)
// Launch 1 fuses: weight collapse (block 0) + edge decode to int2 + passA dots.

#define NMAX  100000
#define EMAX  1600000
#define NFEAT 64
#define NHID  128

__device__ __align__(16) float g_P[NFEAT];
__device__ __align__(16) float g_G[NFEAT];
__device__ __align__(16) float g_S[NFEAT];
__device__ float g_C[2];        // [0]=cb (gated by deg>0), [1]=c2
__device__ int   g_ready = 0;   // set once by prep block (values replay-invariant)

__device__ __align__(16) float4 g_ACC[NMAX];   // (SA, deg, SG, xs)
__device__ __align__(8)  float2 g_XPG[NMAX];   // (xp, xg)
__device__ float g_SB[NMAX];
__device__ __align__(16) int2  g_EDGE[EMAX];   // packed (src, dst)

// ---- local dtype sniff: int64 LE small indices => odd 32-bit words all zero ----
__device__ __forceinline__ int sniff_is64(const int* __restrict__ ei32, int E)
{
    int odd_nonzero = 0;
    #pragma unroll 1
    for (int k = 0; k < 32; k++) {
        long long pos = (1 + (long long)k * ((2LL * E - 2) / 32)) | 1;
        if (ei32[pos] != 0) odd_nonzero++;
    }
    return (odd_nonzero == 0) ? 1 : 0;
}

// ===================== launch 1: prep + decode + passA =====================
__global__ void __launch_bounds__(256) k_init(
    const float* __restrict__ x, const int* __restrict__ ei32,
    const float* __restrict__ Wl1, const float* __restrict__ Wr1,
    const float* __restrict__ b1,
    const float* __restrict__ Wl2, const float* __restrict__ Wr2,
    const float* __restrict__ b2,
    const float* __restrict__ Wfc1, const float* __restrict__ bfc1,
    const float* __restrict__ Wfc2, const float* __restrict__ bfc2,
    int N, int E, int decBlocks)
{
    int b = blockIdx.x;

    // -------- block 0: weight collapse --------
    if (b == 0) {
        __shared__ float sw[NHID], su[NHID], sv[NHID];
        int t = threadIdx.x;
        if (t < NHID) {
            float acc = 0.f;
            #pragma unroll
            for (int c = 0; c < 32; c++) acc += Wfc1[t * 32 + c] * Wfc2[c];
            sw[t] = acc;
        }
        __syncthreads();
        if (t < NHID) {
            float au = 0.f, av = 0.f;
            #pragma unroll 4
            for (int j = 0; j < NHID; j++) {
                float wv = sw[j];
                au += Wl2[t * NHID + j] * wv;
                av += Wr2[t * NHID + j] * wv;
            }
            su[t] = au; sv[t] = av;
        }
        __syncthreads();
        if (t < NFEAT) {
            float p = 0.f, g = 0.f, s = 0.f;
            #pragma unroll 4
            for (int j = 0; j < NHID; j++) {
                float wl = Wl1[t * NHID + j];
                float wr = Wr1[t * NHID + j];
                float uj = su[j], vj = sv[j];
                p += wl * uj;
                g += wr * uj + wl * vj;
                s += wr * vj;
            }
            g_P[t] = p; g_G[t] = g; g_S[t] = s;
        }
        if (t == 0) {
            float cb = 0.f, c2 = 0.f;
            for (int j = 0; j < NHID; j++) {
                cb += b1[j] * su[j];
                c2 += b1[j] * sv[j] + b2[j] * sw[j];
            }
            for (int c = 0; c < 32; c++) c2 += bfc1[c] * Wfc2[c];
            c2 += bfc2[0];
            g_C[0] = cb; g_C[1] = c2;
        }
        __syncthreads();
        if (t == 0) {
            __threadfence();                 // release g_P/g_G/g_S/g_C
            atomicExch(&g_ready, 1);
        }
        return;
    }

    // -------- blocks [1, decBlocks]: edge decode to packed int2 --------
    if (b <= decBlocks) {
        __shared__ int s_is64;
        if (threadIdx.x == 0) s_is64 = sniff_is64(ei32, E);
        __syncthreads();
        int is64 = s_is64;

        long long base = ((long long)(b - 1) * 256 + threadIdx.x) * 4;
        if (base >= E) return;

        if (base + 3 < E) {
            int s[4], d[4];
            if (is64) {
                const long long* p = (const long long*)ei32;
                longlong2 a = __ldg((const longlong2*)(p + base));
                longlong2 c = __ldg((const longlong2*)(p + base + 2));
                longlong2 e = __ldg((const longlong2*)(p + E + base));
                longlong2 f = __ldg((const longlong2*)(p + E + base + 2));
                s[0] = (int)a.x; s[1] = (int)a.y; s[2] = (int)c.x; s[3] = (int)c.y;
                d[0] = (int)e.x; d[1] = (int)e.y; d[2] = (int)f.x; d[3] = (int)f.y;
            } else {
                int4 a = __ldg((const int4*)(ei32 + base));
                int4 c = __ldg((const int4*)(ei32 + E + base));
                s[0] = a.x; s[1] = a.y; s[2] = a.z; s[3] = a.w;
                d[0] = c.x; d[1] = c.y; d[2] = c.z; d[3] = c.w;
            }
            #pragma unroll
            for (int k = 0; k < 4; k++) {
                s[k] = min(max(s[k], 0), N - 1);
                d[k] = min(max(d[k], 0), N - 1);
            }
            ((int4*)g_EDGE)[(base >> 1)]     = make_int4(s[0], d[0], s[1], d[1]);
            ((int4*)g_EDGE)[(base >> 1) + 1] = make_int4(s[2], d[2], s[3], d[3]);
        } else {
            for (long long e = base; e < E; e++) {
                int src, dst;
                if (is64) {
                    src = (int)((const long long*)ei32)[e];
                    dst = (int)((const long long*)ei32)[E + e];
                } else {
                    src = ei32[e]; dst = ei32[E + e];
                }
                src = min(max(src, 0), N - 1);
                dst = min(max(dst, 0), N - 1);
                g_EDGE[e] = make_int2(src, dst);
            }
        }
        return;
    }

    // -------- remaining blocks: passA (half-warp per node) --------
    if (threadIdx.x == 0) {
        while (*(volatile int*)&g_ready == 0) { __nanosleep(64); }
        __threadfence();                     // acquire
    }
    __syncthreads();

    int ab   = b - 1 - decBlocks;
    int node = ab * 16 + (threadIdx.x >> 4);
    int lane = threadIdx.x & 15;
    if (node >= N) return;

    float4 xv = __ldg(((const float4*)x) + (long long)node * 16 + lane);
    float4 pv = ((const float4*)g_P)[lane];
    float4 gv = ((const float4*)g_G)[lane];
    float4 sv = ((const float4*)g_S)[lane];

    float xp = xv.x * pv.x + xv.y * pv.y + xv.z * pv.z + xv.w * pv.w;
    float xg = xv.x * gv.x + xv.y * gv.y + xv.z * gv.z + xv.w * gv.w;
    float xs = xv.x * sv.x + xv.y * sv.y + xv.z * sv.z + xv.w * sv.w;

    #pragma unroll
    for (int off = 8; off; off >>= 1) {
        xp += __shfl_xor_sync(0xffffffffu, xp, off);
        xg += __shfl_xor_sync(0xffffffffu, xg, off);
        xs += __shfl_xor_sync(0xffffffffu, xs, off);
    }
    if (lane == 0) {
        g_XPG[node] = make_float2(xp, xg);
        g_ACC[node] = make_float4(0.f, 0.f, 0.f, xs);
        g_SB[node]  = 0.f;
    }
}

// ===================== scatter 1: ACC[dst] += (xp, 1, xg, 0) =====================
__global__ void __launch_bounds__(256) k_scatter1(int E)
{
    long long base = (long long)(blockIdx.x * 256 + threadIdx.x) * 4;
    if (base >= E) return;

    if (base + 3 < E) {
        int4 q0 = ((const int4*)g_EDGE)[base >> 1];        // (s0,d0,s1,d1)
        int4 q1 = ((const int4*)g_EDGE)[(base >> 1) + 1];  // (s2,d2,s3,d3)
        float2 v0 = __ldg(&g_XPG[q0.x]);
        float2 v1 = __ldg(&g_XPG[q0.z]);
        float2 v2 = __ldg(&g_XPG[q1.x]);
        float2 v3 = __ldg(&g_XPG[q1.z]);
        atomicAdd(&g_ACC[q0.y], make_float4(v0.x, 1.f, v0.y, 0.f));
        atomicAdd(&g_ACC[q0.w], make_float4(v1.x, 1.f, v1.y, 0.f));
        atomicAdd(&g_ACC[q1.y], make_float4(v2.x, 1.f, v2.y, 0.f));
        atomicAdd(&g_ACC[q1.w], make_float4(v3.x, 1.f, v3.y, 0.f));
    } else {
        for (long long e = base; e < E; e++) {
            int2 ed = g_EDGE[e];
            float2 v = __ldg(&g_XPG[ed.x]);
            atomicAdd(&g_ACC[ed.y], make_float4(v.x, 1.f, v.y, 0.f));
        }
    }
}

// ===================== scatter 2: SB[dst] += SA[src]/max(deg[src],1) ==============
__global__ void __launch_bounds__(256) k_scatter2(int E)
{
    long long base = (long long)(blockIdx.x * 256 + threadIdx.x) * 4;
    if (base >= E) return;

    if (base + 3 < E) {
        int4 q0 = ((const int4*)g_EDGE)[base >> 1];
        int4 q1 = ((const int4*)g_EDGE)[(base >> 1) + 1];
        float2 a0 = __ldg((const float2*)&g_ACC[q0.x]);    // (SA, deg)
        float2 a1 = __ldg((const float2*)&g_ACC[q0.z]);
        float2 a2 = __ldg((const float2*)&g_ACC[q1.x]);
        float2 a3 = __ldg((const float2*)&g_ACC[q1.z]);
        atomicAdd(&g_SB[q0.y], a0.x * __frcp_rn(fmaxf(a0.y, 1.f)));
        atomicAdd(&g_SB[q0.w], a1.x * __frcp_rn(fmaxf(a1.y, 1.f)));
        atomicAdd(&g_SB[q1.y], a2.x * __frcp_rn(fmaxf(a2.y, 1.f)));
        atomicAdd(&g_SB[q1.w], a3.x * __frcp_rn(fmaxf(a3.y, 1.f)));
    } else {
        for (long long e = base; e < E; e++) {
            int2 ed = g_EDGE[e];
            float2 a = __ldg((const float2*)&g_ACC[ed.x]);
            atomicAdd(&g_SB[ed.y], a.x * __frcp_rn(fmaxf(a.y, 1.f)));
        }
    }
}

// ===================== final =====================
__global__ void __launch_bounds__(256) k_final(float* __restrict__ out, int n)
{
    int i = blockIdx.x * blockDim.x + threadIdx.x;
    if (i < n) {
        float cb = g_C[0], c2 = g_C[1];
        float4 a = g_ACC[i];                 // (SA, deg, SG, xs)
        float inv = __frcp_rn(fmaxf(a.y, 1.f));
        float res = inv * (g_SB[i] + a.z) + a.w + c2;
        if (a.y > 0.f) res += cb;
        out[i] = res;
    }
}

// ===================== launch =====================
extern "C" void kernel_launch(void* const* d_in, const int* in_sizes, int n_in,
                              void* d_out, int out_size)
{
    const float* x    = (const float*)d_in[0];
    const int*   ei32 = (const int*)d_in[1];
    // d_in[2] = edge_weight (unused by the reference)
    const float* Wl1  = (const float*)d_in[3];
    const float* Wr1  = (const float*)d_in[4];
    const float* b1   = (const float*)d_in[5];
    const float* Wl2  = (const float*)d_in[6];
    const float* Wr2  = (const float*)d_in[7];
    const float* b2   = (const float*)d_in[8];
    const float* Wfc1 = (const float*)d_in[9];
    const float* bfc1 = (const float*)d_in[10];
    const float* Wfc2 = (const float*)d_in[11];
    const float* bfc2 = (const float*)d_in[12];
    float* out = (float*)d_out;

    int N = in_sizes[0] / NFEAT;   // 100000
    int E = in_sizes[2];           // 1600000

    int decB = (E + 1023) / 1024;          // decode blocks (4 edges/thread)
    int aB   = (N + 15) / 16;              // passA blocks (16 nodes/block)

    k_init<<<1 + decB + aB, 256>>>(x, ei32, Wl1, Wr1, b1, Wl2, Wr2, b2,
                                   Wfc1, bfc1, Wfc2, bfc2, N, E, decB);
    k_scatter1<<<decB, 256>>>(E);
    k_scatter2<<<decB, 256>>>(E);
    k_final<<<(N + 255) / 256, 256>>>(out, N);
}